// round 8
// baseline (speedup 1.0000x reference)
#include <cuda_runtime.h>
#include <cuda_fp16.h>
#include <cstdint>

#define IN_F   4096
#define OUT_F  11008
#define TOKENS 8192

// Scratch (static device global: allowed; no runtime allocation)
__device__ __half g_xh[(size_t)TOKENS * IN_F];          // x in fp16, [M, K]

// ---------------------------------------------------------------- common helpers
__device__ __forceinline__ uint32_t smem_u32(const void* p) {
    uint32_t a;
    asm("{ .reg .u64 t; cvta.to.shared.u64 t, %1; cvt.u32.u64 %0, t; }" : "=r"(a) : "l"(p));
    return a;
}

#define SWZ128(o) ((o) ^ (((o) >> 3) & 0x70))

#define MBARRIER_INIT(addr, cnt) \
    asm volatile("mbarrier.init.shared.b64 [%0], %1;" :: "r"((uint32_t)(addr)), "r"((uint32_t)(cnt)) : "memory")
#define MBARRIER_ARRIVE(addr) \
    asm volatile("mbarrier.arrive.shared.b64 _, [%0];" :: "r"((uint32_t)(addr)) : "memory")

#define MBARRIER_WAIT_PARITY(mbar_smem_addr, phase_parity) do {                              \
    uint32_t _mbar = (uint32_t)(mbar_smem_addr);                                             \
    uint32_t _parity = (uint32_t)(phase_parity);                                             \
    uint32_t _done;                                                                          \
    asm volatile("{\n\t.reg .pred p;\n\t"                                                    \
        "mbarrier.try_wait.parity.acquire.cta.shared::cta.b64 p, [%1], %2;\n\t"              \
        "selp.b32 %0, 1, 0, p;\n\t}"                                                         \
        : "=r"(_done) : "r"(_mbar), "r"(_parity) : "memory");                                \
    if (!_done) {                                                                            \
        asm volatile("{\n\t.reg .pred P1;\n\t"                                               \
            "WAIT_LOOP_%=:\n\t"                                                              \
            "mbarrier.try_wait.parity.acquire.cta.shared::cta.b64 P1, [%0], %1, 0x989680;\n\t" \
            "@P1 bra.uni WAIT_DONE_%=;\n\t"                                                  \
            "bra.uni WAIT_LOOP_%=;\n\t"                                                      \
            "WAIT_DONE_%=:\n\t}"                                                             \
            :: "r"(_mbar), "r"(_parity) : "memory");                                         \
    }                                                                                        \
} while (0)

// ---------------------------------------------------------------- tcgen05 helpers (sm_103a pass only)
static constexpr uint64_t SMEM_DESC_BASE_SW128 =
    (uint64_t(2) << 61) | (uint64_t(1) << 46) | (uint64_t(64) << 32) | (uint64_t(1) << 16);
#define MAKE_SMEM_DESC(base_addr) (SMEM_DESC_BASE_SW128 | ((uint64_t)((base_addr) >> 4) & 0x3FFF))

#define TCGEN05_ALLOC(smem_addr, nCols) \
    asm volatile("tcgen05.alloc.cta_group::1.sync.aligned.shared::cta.b32 [%0], %1;" \
                 :: "r"((uint32_t)(smem_addr)), "r"((uint32_t)(nCols)) : "memory")
#define TCGEN05_DEALLOC(tmem_addr, nCols) \
    asm volatile("tcgen05.dealloc.cta_group::1.sync.aligned.b32 %0, %1;" \
                 :: "r"(tmem_addr), "r"((uint32_t)(nCols)))
#define TCGEN05_RELINQUISH() \
    asm volatile("tcgen05.relinquish_alloc_permit.cta_group::1.sync.aligned;")
#define TCGEN05_COMMIT(mbar) \
    asm volatile("tcgen05.commit.cta_group::1.mbarrier::arrive::one.shared::cluster.b64 [%0];" \
                 :: "r"((uint32_t)(mbar)) : "memory")
#define TCGEN05_FENCE_AFTER()  asm volatile("tcgen05.fence::after_thread_sync;" ::: "memory")
#define TCGEN05_FENCE_BEFORE() asm volatile("tcgen05.fence::before_thread_sync;" ::: "memory")
#define TCGEN05_WAIT_LD()      asm volatile("tcgen05.wait::ld.sync.aligned;" ::: "memory")
#define TCGEN05_WAIT_ST()      asm volatile("tcgen05.wait::st.sync.aligned;" ::: "memory")
#define FENCE_PROXY_ASYNC()    asm volatile("fence.proxy.async.shared::cta;" ::: "memory")

#define TCGEN05_LD_32X32B_X32(r, tmem_addr) \
    asm volatile( \
        "tcgen05.ld.sync.aligned.32x32b.x32.b32 " \
        "{%0, %1, %2, %3, %4, %5, %6, %7, " \
        " %8, %9, %10, %11, %12, %13, %14, %15, " \
        " %16, %17, %18, %19, %20, %21, %22, %23, " \
        " %24, %25, %26, %27, %28, %29, %30, %31}, [%32];" \
        : "=r"((r)[0]),  "=r"((r)[1]),  "=r"((r)[2]),  "=r"((r)[3]), \
          "=r"((r)[4]),  "=r"((r)[5]),  "=r"((r)[6]),  "=r"((r)[7]), \
          "=r"((r)[8]),  "=r"((r)[9]),  "=r"((r)[10]), "=r"((r)[11]), \
          "=r"((r)[12]), "=r"((r)[13]), "=r"((r)[14]), "=r"((r)[15]), \
          "=r"((r)[16]), "=r"((r)[17]), "=r"((r)[18]), "=r"((r)[19]), \
          "=r"((r)[20]), "=r"((r)[21]), "=r"((r)[22]), "=r"((r)[23]), \
          "=r"((r)[24]), "=r"((r)[25]), "=r"((r)[26]), "=r"((r)[27]), \
          "=r"((r)[28]), "=r"((r)[29]), "=r"((r)[30]), "=r"((r)[31]) \
        : "r"(tmem_addr))

#define TCGEN05_ST_32X32B_X32(tmem_addr, r) \
    asm volatile( \
        "tcgen05.st.sync.aligned.32x32b.x32.b32 [%0], " \
        "{%1, %2, %3, %4, %5, %6, %7, %8, " \
        " %9, %10, %11, %12, %13, %14, %15, %16, " \
        " %17, %18, %19, %20, %21, %22, %23, %24, " \
        " %25, %26, %27, %28, %29, %30, %31, %32};" \
        :: "r"(tmem_addr), \
           "r"((r)[0]),  "r"((r)[1]),  "r"((r)[2]),  "r"((r)[3]), \
           "r"((r)[4]),  "r"((r)[5]),  "r"((r)[6]),  "r"((r)[7]), \
           "r"((r)[8]),  "r"((r)[9]),  "r"((r)[10]), "r"((r)[11]), \
           "r"((r)[12]), "r"((r)[13]), "r"((r)[14]), "r"((r)[15]), \
           "r"((r)[16]), "r"((r)[17]), "r"((r)[18]), "r"((r)[19]), \
           "r"((r)[20]), "r"((r)[21]), "r"((r)[22]), "r"((r)[23]), \
           "r"((r)[24]), "r"((r)[25]), "r"((r)[26]), "r"((r)[27]), \
           "r"((r)[28]), "r"((r)[29]), "r"((r)[30]), "r"((r)[31]) \
        : "memory")

// TS-mode fp16 MMA: A in TMEM, B via SMEM descriptor, fp32 accum.
__device__ __forceinline__ void mma_f16_ts(uint32_t d, uint32_t a_tmem, uint64_t b,
                                           uint32_t idesc, uint32_t en) {
#if defined(__CUDA_ARCH_FEAT_SM103_ALL)
    asm volatile(
        "{\n\t"
        ".reg .pred p;\n\t"
        "setp.ne.u32 p, %5, 0;\n\t"
        "tcgen05.mma.cta_group::1.kind::f16 [%0], [%1], %2, %3, {%4, %4, %4, %4}, p;\n\t"
        "}"
        :: "r"(d), "r"(a_tmem), "l"(b), "r"(idesc), "r"(0u), "r"(en)
        : "memory");
#endif
}

// ---------------------------------------------------------------- kernel 1: x -> fp16
__global__ void k_convert(const float* __restrict__ x) {
    size_t i = (size_t)blockIdx.x * blockDim.x + threadIdx.x;   // one float4
    const float4 v = reinterpret_cast<const float4*>(x)[i];
    __half2* o = reinterpret_cast<__half2*>(g_xh) + 2 * i;
    o[0] = __floats2half2_rn(v.x, v.y);
    o[1] = __floats2half2_rn(v.z, v.w);
}

// ---------------------------------------------------------------- kernel 2: fused dequant GEMM (TS mode)
// CTA tile M=256, N=128; K-chunk 64; A in TMEM (4 slots x 64 cols), B in SMEM (SW128); 4 stages.
static constexpr int BM = 256, BN = 128, BK = 64;
static constexpr int STAGES = 4;
static constexpr int NPROD = 256;
static constexpr int NTHREADS = 288;
static constexpr int B_BYTES = BN * 128;                 // 16384
static constexpr int SMEM_CTRL = 1024;
static constexpr int EPI_WARP_BYTES = 16896;             // 32 rows x 528B
static constexpr int SMEM_TOTAL = SMEM_CTRL + 8 * EPI_WARP_BYTES; // 136192 (covers 4x16KB stages)
static constexpr int K_ITERS = IN_F / BK;                // 64
static constexpr int TMEM_D = 256;                       // D cols 256..511; A slots 0..255
// idesc: f32 accum (1<<4), fp16 A/B (0), N/8 << 17, M/16 << 24  (per-dispatch M=128)
static constexpr uint32_t IDESC = (1u << 4) | ((BN / 8) << 17) | ((128 / 16) << 24);
#define FULL_BAR(s)  (smem_base + 16 + 16 * (s))
#define EMPTY_BAR(s) (smem_base + 24 + 16 * (s))

__global__ __launch_bounds__(NTHREADS, 1) void k_gemm(const int* __restrict__ qweight,
                                                      const int* __restrict__ qzeros,
                                                      const float* __restrict__ scales,
                                                      const float* __restrict__ bias,
                                                      float* __restrict__ out) {
    extern __shared__ char smem[];
    const uint32_t smem_base = smem_u32(smem);
    const int tid = threadIdx.x;
    const int wid = tid >> 5;
    const int lid = tid & 31;
    const int NB = OUT_F / BN;                           // 86
    const int n0 = (blockIdx.x % NB) * BN;
    const int m0 = (blockIdx.x / NB) * BM;

#if defined(__CUDA_ARCH_FEAT_SM103_ALL)
    // =================== warp-specialized TS-mode pipeline ===================
    if (wid == 0) TCGEN05_ALLOC(smem_base + 0, 512);
    if (tid == 0) {
#pragma unroll
        for (int s = 0; s < STAGES; s++) {
            MBARRIER_INIT(FULL_BAR(s), NPROD);           // 256 producer arrives
            MBARRIER_INIT(EMPTY_BAR(s), 1);
            MBARRIER_ARRIVE(EMPTY_BAR(s));               // pre-arm: completion #0, parity 0
        }
    }
    __syncthreads();
    uint32_t tmem;
    asm volatile("ld.shared.b32 %0, [%1];" : "=r"(tmem) : "r"(smem_base));

    if (tid < NPROD) {
        // -------- producer: A row (LDG->STTM) + half a B column (dequant->STS) --------
        const int nc = tid & 127;                        // B column within tile
        const int n = n0 + nc;
        const int khalf = tid >> 7;                      // which 32-k half of the B chunk
        const int half = tid >> 7;                       // A M-half (row tid)
        const uint32_t warp_offset = (uint32_t)(((tid & 127) >> 5) << 21);
        const uint32_t a_tm_base = tmem + half * 32 + warp_offset;
        const __half* arow = g_xh + (size_t)(m0 + tid) * IN_F;

        uint32_t abuf[32];                               // 64 fp16 = this row's next A chunk
        uint32_t qbuf[2][4];
        __half2 scbuf[2], zcbuf[2];

        auto ldg_A = [&](int j) {
            const uint4* src = reinterpret_cast<const uint4*>(arow + j * BK);
#pragma unroll
            for (int i = 0; i < 8; i++) {
                uint4 v = __ldg(src + i);
                abuf[4 * i + 0] = v.x; abuf[4 * i + 1] = v.y;
                abuf[4 * i + 2] = v.z; abuf[4 * i + 3] = v.w;
            }
        };
        auto ldg_q = [&](int j, int b) {
            const int* qw = qweight + (size_t)(j * 8 + khalf * 4) * OUT_F + n;
#pragma unroll
            for (int i = 0; i < 4; i++) qbuf[b][i] = (uint32_t)__ldg(qw + (size_t)i * OUT_F);
            int g = j >> 1;                              // group (GSIZE=128, BK=64)
            float sc = __ldg(scales + (size_t)g * OUT_F + n);
            uint32_t qz = (uint32_t)__ldg(qzeros + (size_t)g * (OUT_F / 8) + (n >> 3));
            int z1 = (int)((qz >> ((n & 7) * 4)) & 0xF) + 1;
            scbuf[b] = __half2half2(__float2half_rn(sc));
            zcbuf[b] = __half2half2(__float2half_rn((float)(1024 + z1)));  // exact in fp16
        };

        ldg_A(0);
        ldg_q(0, 0);
        ldg_q(1, 1);

        for (int it = 0; it < K_ITERS; ++it) {
            const int s = it & (STAGES - 1);
            const int r = it >> 2;
            MBARRIER_WAIT_PARITY(EMPTY_BAR(s), r & 1);   // stage free (MMA round r-1 done)

            // A: regs -> TMEM slot s (warp-collective x32 = 64 fp16)
            TCGEN05_ST_32X32B_X32(a_tm_base + s * 64, abuf);
            TCGEN05_WAIT_ST();

            // B: dequant 32 k-values -> row nc, k-offset khalf*64..+64B (SW128)
            {
                char* bptr = smem + SMEM_CTRL + s * B_BYTES;
                const int b = it & 1;
                const __half2 sc2 = scbuf[b], zc2 = zcbuf[b];
#pragma unroll
                for (int i = 0; i < 4; i++) {
                    uint32_t qv = qbuf[b][i];
                    uint32_t w[4];
#pragma unroll
                    for (int p = 0; p < 4; p++) {
                        uint32_t t = qv >> (8 * p);
                        uint32_t u = (t & 0xFu) | ((t & 0xF0u) << 12) | 0x64006400u;
                        __half2 vh = *reinterpret_cast<__half2*>(&u);
                        __half2 dh = __hsub2(vh, zc2);                       // exact v - z1
                        __half2 wh = __hmul2(dh, sc2);
                        w[p] = *reinterpret_cast<uint32_t*>(&wh);
                    }
                    uint32_t off = (uint32_t)(nc * 128 + khalf * 64 + i * 16);
                    *reinterpret_cast<uint4*>(bptr + SWZ128(off)) = make_uint4(w[0], w[1], w[2], w[3]);
                }
            }
            TCGEN05_FENCE_BEFORE();
            MBARRIER_ARRIVE(FULL_BAR(s));

            // prefetch next inputs (latency hidden by pipeline slack)
            if (it + 1 < K_ITERS) ldg_A(it + 1);
            if (it + 2 < K_ITERS) ldg_q(it + 2, it & 1);
        }
    } else if (tid == NPROD) {
        // -------- MMA thread --------
        for (int it = 0; it < K_ITERS; ++it) {
            const int s = it & (STAGES - 1);
            const int r = it >> 2;
            MBARRIER_WAIT_PARITY(FULL_BAR(s), r & 1);
            FENCE_PROXY_ASYNC();                          // STS B -> async proxy
            TCGEN05_FENCE_AFTER();                        // STTM A visibility
            uint64_t bd = MAKE_SMEM_DESC(smem_base + SMEM_CTRL + s * B_BYTES);
            const uint32_t a_s = tmem + s * 64;
#pragma unroll
            for (int kk = 0; kk < 4; kk++) {              // 4 x K=16 steps
                mma_f16_ts(tmem + TMEM_D,       a_s + kk * 8,      bd + kk * 2, IDESC, (uint32_t)(it | kk));
                mma_f16_ts(tmem + TMEM_D + 128, a_s + 32 + kk * 8, bd + kk * 2, IDESC, (uint32_t)(it | kk));
            }
            TCGEN05_COMMIT(EMPTY_BAR(s));
        }
    }

    // Last commit: it=63 -> empty[3] completion #16 -> parity 0 (covers whole in-order MMA chain)
    MBARRIER_WAIT_PARITY(EMPTY_BAR(3), 0);
    __syncthreads();
    TCGEN05_FENCE_AFTER();

    // ---- epilogue (warps 0-7): TMEM -> SMEM transpose -> coalesced STG ----
    if (wid < 8) {
        char* wsm = smem + SMEM_CTRL + wid * EPI_WARP_BYTES;   // 32 rows x 132 f32 (528B)
        const uint32_t dz = tmem + TMEM_D + (uint32_t)((wid >> 2) * 128);
        const int mrow = m0 + (wid >> 2) * 128 + (wid & 3) * 32;
#pragma unroll
        for (int ch = 0; ch < 4; ++ch) {                 // 4 x 32-col chunks
            uint32_t d[32];
            TCGEN05_LD_32X32B_X32(d, dz + ch * 32);
            TCGEN05_WAIT_LD();
#pragma unroll
            for (int c = 0; c < 32; c += 4)
                *reinterpret_cast<uint4*>(wsm + lid * 528 + (ch * 32 + c) * 4) =
                    make_uint4(d[c], d[c + 1], d[c + 2], d[c + 3]);
        }
        __syncwarp();
        float4 b4 = *reinterpret_cast<const float4*>(bias + n0 + lid * 4);
#pragma unroll 4
        for (int j = 0; j < 32; ++j) {
            float4 v = *reinterpret_cast<float4*>(wsm + j * 528 + lid * 16);
            v.x += b4.x; v.y += b4.y; v.z += b4.z; v.w += b4.w;
            *reinterpret_cast<float4*>(out + (size_t)(mrow + j) * OUT_F + n0 + lid * 4) = v;
        }
    }

    TCGEN05_FENCE_BEFORE();
    __syncthreads();
    if (wid == 0) {
        TCGEN05_RELINQUISH();
        TCGEN05_DEALLOC(tmem, 512);
    }
#else
    // =================== trivial fallback (never selected on sm_103a hardware) ===================
    if (tid < 128) {
        const int nn = n0 + tid;
        for (int m = m0; m < m0 + BM; ++m) {
            float acc = bias[nn];
            for (int k = 0; k < IN_F; ++k) {
                int g = k >> 7;
                uint32_t q = (uint32_t)qweight[(size_t)(k >> 3) * OUT_F + nn];
                int v = (int)((q >> ((k & 7) * 4)) & 0xF);
                uint32_t qz = (uint32_t)qzeros[(size_t)g * (OUT_F / 8) + (nn >> 3)];
                int z1 = (int)((qz >> ((nn & 7) * 4)) & 0xF) + 1;
                acc += __half2float(g_xh[(size_t)m * IN_F + k]) * (scales[(size_t)g * OUT_F + nn] * (float)(v - z1));
            }
            out[(size_t)m * OUT_F + nn] = acc;
        }
    }
#endif
}

// ---------------------------------------------------------------- launch
extern "C" void kernel_launch(void* const* d_in, const int* in_sizes, int n_in,
                              void* d_out, int out_size) {
    const float* x       = (const float*)d_in[0];
    const int*   qweight = (const int*)  d_in[1];
    const int*   qzeros  = (const int*)  d_in[2];
    const float* scales  = (const float*)d_in[3];
    // d_in[4] = g_idx (implicitly k/128, hardcoded)
    const float* bias    = (const float*)d_in[5];
    float* out = (float*)d_out;

    k_convert<<<(TOKENS * IN_F) / (256 * 4), 256>>>(x);

    cudaFuncSetAttribute(k_gemm, cudaFuncAttributeMaxDynamicSharedMemorySize, SMEM_TOTAL);
    k_gemm<<<(OUT_F / BN) * (TOKENS / BM), NTHREADS, SMEM_TOTAL>>>(qweight, qzeros, scales, bias, out);
}

// round 9
// speedup vs baseline: 1.6108x; 1.6108x over previous
#include <cuda_runtime.h>
#include <cuda_fp16.h>
#include <cstdint>

#define IN_F   4096
#define OUT_F  11008
#define TOKENS 8192

// x in fp16, 16B-chunk transposed: uint4 index [c][m], c = k/8 (0..511), m = row (0..8191)
__device__ uint4 g_xh_T[(size_t)(IN_F / 8) * TOKENS];

// ---------------------------------------------------------------- common helpers
__device__ __forceinline__ uint32_t smem_u32(const void* p) {
    uint32_t a;
    asm("{ .reg .u64 t; cvta.to.shared.u64 t, %1; cvt.u32.u64 %0, t; }" : "=r"(a) : "l"(p));
    return a;
}

#define SWZ128(o) ((o) ^ (((o) >> 3) & 0x70))

#define MBARRIER_INIT(addr, cnt) \
    asm volatile("mbarrier.init.shared.b64 [%0], %1;" :: "r"((uint32_t)(addr)), "r"((uint32_t)(cnt)) : "memory")
#define MBARRIER_ARRIVE(addr) \
    asm volatile("mbarrier.arrive.shared.b64 _, [%0];" :: "r"((uint32_t)(addr)) : "memory")

#define MBARRIER_WAIT_PARITY(mbar_smem_addr, phase_parity) do {                              \
    uint32_t _mbar = (uint32_t)(mbar_smem_addr);                                             \
    uint32_t _parity = (uint32_t)(phase_parity);                                             \
    uint32_t _done;                                                                          \
    asm volatile("{\n\t.reg .pred p;\n\t"                                                    \
        "mbarrier.try_wait.parity.acquire.cta.shared::cta.b64 p, [%1], %2;\n\t"              \
        "selp.b32 %0, 1, 0, p;\n\t}"                                                         \
        : "=r"(_done) : "r"(_mbar), "r"(_parity) : "memory");                                \
    if (!_done) {                                                                            \
        asm volatile("{\n\t.reg .pred P1;\n\t"                                               \
            "WAIT_LOOP_%=:\n\t"                                                              \
            "mbarrier.try_wait.parity.acquire.cta.shared::cta.b64 P1, [%0], %1, 0x989680;\n\t" \
            "@P1 bra.uni WAIT_DONE_%=;\n\t"                                                  \
            "bra.uni WAIT_LOOP_%=;\n\t"                                                      \
            "WAIT_DONE_%=:\n\t}"                                                             \
            :: "r"(_mbar), "r"(_parity) : "memory");                                         \
    }                                                                                        \
} while (0)

// ---------------------------------------------------------------- tcgen05 helpers (sm_103a pass only)
static constexpr uint64_t SMEM_DESC_BASE_SW128 =
    (uint64_t(2) << 61) | (uint64_t(1) << 46) | (uint64_t(64) << 32) | (uint64_t(1) << 16);
#define MAKE_SMEM_DESC(base_addr) (SMEM_DESC_BASE_SW128 | ((uint64_t)((base_addr) >> 4) & 0x3FFF))

#define TCGEN05_ALLOC(smem_addr, nCols) \
    asm volatile("tcgen05.alloc.cta_group::1.sync.aligned.shared::cta.b32 [%0], %1;" \
                 :: "r"((uint32_t)(smem_addr)), "r"((uint32_t)(nCols)) : "memory")
#define TCGEN05_DEALLOC(tmem_addr, nCols) \
    asm volatile("tcgen05.dealloc.cta_group::1.sync.aligned.b32 %0, %1;" \
                 :: "r"(tmem_addr), "r"((uint32_t)(nCols)))
#define TCGEN05_RELINQUISH() \
    asm volatile("tcgen05.relinquish_alloc_permit.cta_group::1.sync.aligned;")
#define TCGEN05_COMMIT(mbar) \
    asm volatile("tcgen05.commit.cta_group::1.mbarrier::arrive::one.shared::cluster.b64 [%0];" \
                 :: "r"((uint32_t)(mbar)) : "memory")
#define TCGEN05_FENCE_AFTER()  asm volatile("tcgen05.fence::after_thread_sync;" ::: "memory")
#define TCGEN05_FENCE_BEFORE() asm volatile("tcgen05.fence::before_thread_sync;" ::: "memory")
#define TCGEN05_WAIT_LD()      asm volatile("tcgen05.wait::ld.sync.aligned;" ::: "memory")
#define TCGEN05_WAIT_ST()      asm volatile("tcgen05.wait::st.sync.aligned;" ::: "memory")
#define FENCE_PROXY_ASYNC()    asm volatile("fence.proxy.async.shared::cta;" ::: "memory")

#define TCGEN05_LD_32X32B_X32(r, tmem_addr) \
    asm volatile( \
        "tcgen05.ld.sync.aligned.32x32b.x32.b32 " \
        "{%0, %1, %2, %3, %4, %5, %6, %7, " \
        " %8, %9, %10, %11, %12, %13, %14, %15, " \
        " %16, %17, %18, %19, %20, %21, %22, %23, " \
        " %24, %25, %26, %27, %28, %29, %30, %31}, [%32];" \
        : "=r"((r)[0]),  "=r"((r)[1]),  "=r"((r)[2]),  "=r"((r)[3]), \
          "=r"((r)[4]),  "=r"((r)[5]),  "=r"((r)[6]),  "=r"((r)[7]), \
          "=r"((r)[8]),  "=r"((r)[9]),  "=r"((r)[10]), "=r"((r)[11]), \
          "=r"((r)[12]), "=r"((r)[13]), "=r"((r)[14]), "=r"((r)[15]), \
          "=r"((r)[16]), "=r"((r)[17]), "=r"((r)[18]), "=r"((r)[19]), \
          "=r"((r)[20]), "=r"((r)[21]), "=r"((r)[22]), "=r"((r)[23]), \
          "=r"((r)[24]), "=r"((r)[25]), "=r"((r)[26]), "=r"((r)[27]), \
          "=r"((r)[28]), "=r"((r)[29]), "=r"((r)[30]), "=r"((r)[31]) \
        : "r"(tmem_addr))

#define TCGEN05_ST_32X32B_X32(tmem_addr, r) \
    asm volatile( \
        "tcgen05.st.sync.aligned.32x32b.x32.b32 [%0], " \
        "{%1, %2, %3, %4, %5, %6, %7, %8, " \
        " %9, %10, %11, %12, %13, %14, %15, %16, " \
        " %17, %18, %19, %20, %21, %22, %23, %24, " \
        " %25, %26, %27, %28, %29, %30, %31, %32};" \
        :: "r"(tmem_addr), \
           "r"((r)[0]),  "r"((r)[1]),  "r"((r)[2]),  "r"((r)[3]), \
           "r"((r)[4]),  "r"((r)[5]),  "r"((r)[6]),  "r"((r)[7]), \
           "r"((r)[8]),  "r"((r)[9]),  "r"((r)[10]), "r"((r)[11]), \
           "r"((r)[12]), "r"((r)[13]), "r"((r)[14]), "r"((r)[15]), \
           "r"((r)[16]), "r"((r)[17]), "r"((r)[18]), "r"((r)[19]), \
           "r"((r)[20]), "r"((r)[21]), "r"((r)[22]), "r"((r)[23]), \
           "r"((r)[24]), "r"((r)[25]), "r"((r)[26]), "r"((r)[27]), \
           "r"((r)[28]), "r"((r)[29]), "r"((r)[30]), "r"((r)[31]) \
        : "memory")

// TS-mode fp16 MMA: A in TMEM, B via SMEM descriptor, fp32 accum.
__device__ __forceinline__ void mma_f16_ts(uint32_t d, uint32_t a_tmem, uint64_t b,
                                           uint32_t idesc, uint32_t en) {
#if defined(__CUDA_ARCH_FEAT_SM103_ALL)
    asm volatile(
        "{\n\t"
        ".reg .pred p;\n\t"
        "setp.ne.u32 p, %5, 0;\n\t"
        "tcgen05.mma.cta_group::1.kind::f16 [%0], [%1], %2, %3, {%4, %4, %4, %4}, p;\n\t"
        "}"
        :: "r"(d), "r"(a_tmem), "l"(b), "r"(idesc), "r"(0u), "r"(en)
        : "memory");
#endif
}

// ---------------------------------------------------------------- kernel 1: x -> fp16, chunk-transposed
// out[c][m] (uint4) = half8(x[m][c*8 .. c*8+7]). SMEM-tiled 32x32 transpose, both sides coalesced.
__global__ __launch_bounds__(256) void k_convert(const float* __restrict__ x) {
    __shared__ uint4 tile[32][33];
    const int c0 = blockIdx.x * 32;                      // chunk tile (16 tiles)
    const int m0 = blockIdx.y * 32;                      // row tile (256 tiles)
    const int tid = threadIdx.x;
#pragma unroll
    for (int p = 0; p < 4; ++p) {
        int idx = p * 256 + tid;
        int cc = idx & 31, mm = idx >> 5;                // mm in 0..31 over 4 passes
        const float4* src = reinterpret_cast<const float4*>(
            x + (size_t)(m0 + mm) * IN_F + (size_t)(c0 + cc) * 8);
        float4 a = __ldg(src), b = __ldg(src + 1);
        uint4 o;
        o.x = *reinterpret_cast<uint32_t*>(&(__half2&)*(__half2[]){__floats2half2_rn(a.x, a.y)});
        // (packed below without UB helpers)
        __half2 h0 = __floats2half2_rn(a.x, a.y);
        __half2 h1 = __floats2half2_rn(a.z, a.w);
        __half2 h2 = __floats2half2_rn(b.x, b.y);
        __half2 h3 = __floats2half2_rn(b.z, b.w);
        o.x = *reinterpret_cast<uint32_t*>(&h0);
        o.y = *reinterpret_cast<uint32_t*>(&h1);
        o.z = *reinterpret_cast<uint32_t*>(&h2);
        o.w = *reinterpret_cast<uint32_t*>(&h3);
        tile[cc][mm] = o;
    }
    __syncthreads();
#pragma unroll
    for (int p = 0; p < 4; ++p) {
        int idx = p * 256 + tid;
        int mm = idx & 31, cc = idx >> 5;
        g_xh_T[(size_t)(c0 + cc) * TOKENS + (m0 + mm)] = tile[cc][mm];
    }
}

// ---------------------------------------------------------------- kernel 2: fused dequant GEMM (TS mode)
// CTA tile M=256, N=128; K-chunk 64; A in TMEM (4 slots x 64 cols), B in SMEM (SW128); 4 stages.
static constexpr int BM = 256, BN = 128, BK = 64;
static constexpr int STAGES = 4;
static constexpr int NPROD = 256;
static constexpr int NTHREADS = 288;
static constexpr int B_BYTES = BN * 128;                 // 16384
static constexpr int SMEM_CTRL = 1024;
static constexpr int EPI_WARP_BYTES = 16896;             // 32 rows x 528B
static constexpr int SMEM_TOTAL = SMEM_CTRL + 8 * EPI_WARP_BYTES; // 136192 (covers 4x16KB stages)
static constexpr int K_ITERS = IN_F / BK;                // 64
static constexpr int TMEM_D = 256;                       // D cols 256..511; A slots 0..255
static constexpr uint32_t IDESC = (1u << 4) | ((BN / 8) << 17) | ((128 / 16) << 24);
#define FULL_BAR(s)  (smem_base + 16 + 16 * (s))
#define EMPTY_BAR(s) (smem_base + 24 + 16 * (s))

__global__ __launch_bounds__(NTHREADS, 1) void k_gemm(const int* __restrict__ qweight,
                                                      const int* __restrict__ qzeros,
                                                      const float* __restrict__ scales,
                                                      const float* __restrict__ bias,
                                                      float* __restrict__ out) {
    extern __shared__ char smem[];
    const uint32_t smem_base = smem_u32(smem);
    const int tid = threadIdx.x;
    const int wid = tid >> 5;
    const int lid = tid & 31;
    const int NB = OUT_F / BN;                           // 86
    const int n0 = (blockIdx.x % NB) * BN;
    const int m0 = (blockIdx.x / NB) * BM;

#if defined(__CUDA_ARCH_FEAT_SM103_ALL)
    // =================== warp-specialized TS-mode pipeline ===================
    if (wid == 0) TCGEN05_ALLOC(smem_base + 0, 512);
    if (tid == 0) {
#pragma unroll
        for (int s = 0; s < STAGES; s++) {
            MBARRIER_INIT(FULL_BAR(s), NPROD);           // 256 producer arrives
            MBARRIER_INIT(EMPTY_BAR(s), 1);
            MBARRIER_ARRIVE(EMPTY_BAR(s));               // pre-arm: completion #0, parity 0
        }
    }
    __syncthreads();
    uint32_t tmem;
    asm volatile("ld.shared.b32 %0, [%1];" : "=r"(tmem) : "r"(smem_base));

    if (tid < NPROD) {
        // -------- producer: A row (coalesced LDG -> STTM) + half a B column (dequant -> STS) --------
        const int nc = tid & 127;                        // B column within tile
        const int n = n0 + nc;
        const int khalf = tid >> 7;                      // which 32-k half of the B chunk
        const uint32_t warp_offset = (uint32_t)(((tid & 127) >> 5) << 21);
        const uint32_t a_tm_base = tmem + (uint32_t)((tid >> 7) * 32) + warp_offset;
        const uint4* a16 = g_xh_T + (size_t)(m0 + tid);  // + (it*8+s)*TOKENS per chunk

        uint32_t abuf[32];                               // 64 fp16 = this row's next A chunk
        uint32_t qbuf[2][4];
        __half2 scbuf[2], zcbuf[2];

        auto ldg_A = [&](int j) {
#pragma unroll
            for (int s = 0; s < 8; s++) {                // lanes read consecutive m: 512B coalesced
                uint4 v = __ldg(a16 + (size_t)(j * 8 + s) * TOKENS);
                abuf[4 * s + 0] = v.x; abuf[4 * s + 1] = v.y;
                abuf[4 * s + 2] = v.z; abuf[4 * s + 3] = v.w;
            }
        };
        auto ldg_q = [&](int j, int b) {
            const int* qw = qweight + (size_t)(j * 8 + khalf * 4) * OUT_F + n;
#pragma unroll
            for (int i = 0; i < 4; i++) qbuf[b][i] = (uint32_t)__ldg(qw + (size_t)i * OUT_F);
            int g = j >> 1;                              // group (GSIZE=128, BK=64)
            float sc = __ldg(scales + (size_t)g * OUT_F + n);
            uint32_t qz = (uint32_t)__ldg(qzeros + (size_t)g * (OUT_F / 8) + (n >> 3));
            int z1 = (int)((qz >> ((n & 7) * 4)) & 0xF) + 1;
            scbuf[b] = __half2half2(__float2half_rn(sc));
            zcbuf[b] = __half2half2(__float2half_rn((float)(1024 + z1)));  // exact in fp16
        };

        ldg_A(0);
        ldg_q(0, 0);
        ldg_q(1, 1);

        for (int it = 0; it < K_ITERS; ++it) {
            const int s = it & (STAGES - 1);
            const int r = it >> 2;
            MBARRIER_WAIT_PARITY(EMPTY_BAR(s), r & 1);   // stage free (MMA round r-1 done)

            // A: regs -> TMEM slot s (warp-collective x32 = 64 fp16)
            TCGEN05_ST_32X32B_X32(a_tm_base + s * 64, abuf);
            TCGEN05_WAIT_ST();

            // B: dequant 32 k-values -> row nc, k-offset khalf*64 bytes (SW128)
            {
                char* bptr = smem + SMEM_CTRL + s * B_BYTES;
                const int b = it & 1;
                const __half2 sc2 = scbuf[b], zc2 = zcbuf[b];
#pragma unroll
                for (int i = 0; i < 4; i++) {
                    uint32_t qv = qbuf[b][i];
                    uint32_t w[4];
#pragma unroll
                    for (int p = 0; p < 4; p++) {
                        uint32_t t = qv >> (8 * p);
                        uint32_t u = (t & 0xFu) | ((t & 0xF0u) << 12) | 0x64006400u;
                        __half2 vh = *reinterpret_cast<__half2*>(&u);
                        __half2 dh = __hsub2(vh, zc2);                       // exact v - z1
                        __half2 wh = __hmul2(dh, sc2);
                        w[p] = *reinterpret_cast<uint32_t*>(&wh);
                    }
                    uint32_t off = (uint32_t)(nc * 128 + khalf * 64 + i * 16);
                    *reinterpret_cast<uint4*>(bptr + SWZ128(off)) = make_uint4(w[0], w[1], w[2], w[3]);
                }
            }
            TCGEN05_FENCE_BEFORE();
            MBARRIER_ARRIVE(FULL_BAR(s));

            // prefetch next inputs (latency hidden by pipeline slack)
            if (it + 1 < K_ITERS) ldg_A(it + 1);
            if (it + 2 < K_ITERS) ldg_q(it + 2, it & 1);
        }
    } else if (tid == NPROD) {
        // -------- MMA thread --------
        for (int it = 0; it < K_ITERS; ++it) {
            const int s = it & (STAGES - 1);
            const int r = it >> 2;
            MBARRIER_WAIT_PARITY(FULL_BAR(s), r & 1);
            FENCE_PROXY_ASYNC();                          // STS B -> async proxy
            TCGEN05_FENCE_AFTER();                        // STTM A visibility
            uint64_t bd = MAKE_SMEM_DESC(smem_base + SMEM_CTRL + s * B_BYTES);
            const uint32_t a_s = tmem + s * 64;
#pragma unroll
            for (int kk = 0; kk < 4; kk++) {              // 4 x K=16 steps
                mma_f16_ts(tmem + TMEM_D,       a_s + kk * 8,      bd + kk * 2, IDESC, (uint32_t)(it | kk));
                mma_f16_ts(tmem + TMEM_D + 128, a_s + 32 + kk * 8, bd + kk * 2, IDESC, (uint32_t)(it | kk));
            }
            TCGEN05_COMMIT(EMPTY_BAR(s));
        }
    }

    // Last commit: it=63 -> empty[3] completion #16 -> parity 0 (covers whole in-order MMA chain)
    MBARRIER_WAIT_PARITY(EMPTY_BAR(3), 0);
    __syncthreads();
    TCGEN05_FENCE_AFTER();

    // ---- epilogue (warps 0-7): TMEM -> SMEM transpose -> coalesced STG ----
    if (wid < 8) {
        char* wsm = smem + SMEM_CTRL + wid * EPI_WARP_BYTES;   // 32 rows x 132 f32 (528B)
        const uint32_t dz = tmem + TMEM_D + (uint32_t)((wid >> 2) * 128);
        const int mrow = m0 + (wid >> 2) * 128 + (wid & 3) * 32;
#pragma unroll
        for (int ch = 0; ch < 4; ++ch) {                 // 4 x 32-col chunks
            uint32_t d[32];
            TCGEN05_LD_32X32B_X32(d, dz + ch * 32);
            TCGEN05_WAIT_LD();
#pragma unroll
            for (int c = 0; c < 32; c += 4)
                *reinterpret_cast<uint4*>(wsm + lid * 528 + (ch * 32 + c) * 4) =
                    make_uint4(d[c], d[c + 1], d[c + 2], d[c + 3]);
        }
        __syncwarp();
        float4 b4 = *reinterpret_cast<const float4*>(bias + n0 + lid * 4);
#pragma unroll 4
        for (int j = 0; j < 32; ++j) {
            float4 v = *reinterpret_cast<float4*>(wsm + j * 528 + lid * 16);
            v.x += b4.x; v.y += b4.y; v.z += b4.z; v.w += b4.w;
            *reinterpret_cast<float4*>(out + (size_t)(mrow + j) * OUT_F + n0 + lid * 4) = v;
        }
    }

    TCGEN05_FENCE_BEFORE();
    __syncthreads();
    if (wid == 0) {
        TCGEN05_RELINQUISH();
        TCGEN05_DEALLOC(tmem, 512);
    }
#else
    // =================== trivial fallback (never selected on sm_103a hardware) ===================
    if (tid < 128) {
        const int nn = n0 + tid;
        for (int m = m0; m < m0 + BM; ++m) {
            float acc = bias[nn];
            for (int k = 0; k < IN_F; ++k) {
                int g = k >> 7;
                uint32_t q = (uint32_t)qweight[(size_t)(k >> 3) * OUT_F + nn];
                int v = (int)((q >> ((k & 7) * 4)) & 0xF);
                uint32_t qz = (uint32_t)qzeros[(size_t)g * (OUT_F / 8) + (nn >> 3)];
                int z1 = (int)((qz >> ((nn & 7) * 4)) & 0xF) + 1;
                const uint4 xv = g_xh_T[(size_t)(k >> 3) * TOKENS + m];
                const __half* xh = reinterpret_cast<const __half*>(&xv);
                acc += __half2float(xh[k & 7]) * (scales[(size_t)g * OUT_F + nn] * (float)(v - z1));
            }
            out[(size_t)m * OUT_F + nn] = acc;
        }
    }
#endif
}

// ---------------------------------------------------------------- launch
extern "C" void kernel_launch(void* const* d_in, const int* in_sizes, int n_in,
                              void* d_out, int out_size) {
    const float* x       = (const float*)d_in[0];
    const int*   qweight = (const int*)  d_in[1];
    const int*   qzeros  = (const int*)  d_in[2];
    const float* scales  = (const float*)d_in[3];
    // d_in[4] = g_idx (implicitly k/128, hardcoded)
    const float* bias    = (const float*)d_in[5];
    float* out = (float*)d_out;

    k_convert<<<dim3(IN_F / 8 / 32, TOKENS / 32), 256>>>(x);

    cudaFuncSetAttribute(k_gemm, cudaFuncAttributeMaxDynamicSharedMemorySize, SMEM_TOTAL);
    k_gemm<<<(OUT_F / BN) * (TOKENS / BM), NTHREADS, SMEM_TOTAL>>>(qweight, qzeros, scales, bias, out);
}

// round 10
// speedup vs baseline: 2.3213x; 1.4410x over previous
#include <cuda_runtime.h>
#include <cuda_fp16.h>
#include <cstdint>

#define IN_F   4096
#define OUT_F  11008
#define TOKENS 8192

// x in fp16, 16B-chunk transposed: uint4 index [c][m], c = k/8 (0..511), m = row (0..8191)
__device__ uint4 g_xh_T[(size_t)(IN_F / 8) * TOKENS];

// ---------------------------------------------------------------- common helpers
__device__ __forceinline__ uint32_t smem_u32(const void* p) {
    uint32_t a;
    asm("{ .reg .u64 t; cvta.to.shared.u64 t, %1; cvt.u32.u64 %0, t; }" : "=r"(a) : "l"(p));
    return a;
}

#define SWZ128(o) ((o) ^ (((o) >> 3) & 0x70))

#define MBARRIER_INIT(addr, cnt) \
    asm volatile("mbarrier.init.shared.b64 [%0], %1;" :: "r"((uint32_t)(addr)), "r"((uint32_t)(cnt)) : "memory")
#define MBARRIER_ARRIVE(addr) \
    asm volatile("mbarrier.arrive.shared.b64 _, [%0];" :: "r"((uint32_t)(addr)) : "memory")

#define MBARRIER_WAIT_PARITY(mbar_smem_addr, phase_parity) do {                              \
    uint32_t _mbar = (uint32_t)(mbar_smem_addr);                                             \
    uint32_t _parity = (uint32_t)(phase_parity);                                             \
    uint32_t _done;                                                                          \
    asm volatile("{\n\t.reg .pred p;\n\t"                                                    \
        "mbarrier.try_wait.parity.acquire.cta.shared::cta.b64 p, [%1], %2;\n\t"              \
        "selp.b32 %0, 1, 0, p;\n\t}"                                                         \
        : "=r"(_done) : "r"(_mbar), "r"(_parity) : "memory");                                \
    if (!_done) {                                                                            \
        asm volatile("{\n\t.reg .pred P1;\n\t"                                               \
            "WAIT_LOOP_%=:\n\t"                                                              \
            "mbarrier.try_wait.parity.acquire.cta.shared::cta.b64 P1, [%0], %1, 0x989680;\n\t" \
            "@P1 bra.uni WAIT_DONE_%=;\n\t"                                                  \
            "bra.uni WAIT_LOOP_%=;\n\t"                                                      \
            "WAIT_DONE_%=:\n\t}"                                                             \
            :: "r"(_mbar), "r"(_parity) : "memory");                                         \
    }                                                                                        \
} while (0)

// ---------------------------------------------------------------- tcgen05 helpers (sm_103a pass only)
static constexpr uint64_t SMEM_DESC_BASE_SW128 =
    (uint64_t(2) << 61) | (uint64_t(1) << 46) | (uint64_t(64) << 32) | (uint64_t(1) << 16);
#define MAKE_SMEM_DESC(base_addr) (SMEM_DESC_BASE_SW128 | ((uint64_t)((base_addr) >> 4) & 0x3FFF))

#define TCGEN05_ALLOC(smem_addr, nCols) \
    asm volatile("tcgen05.alloc.cta_group::1.sync.aligned.shared::cta.b32 [%0], %1;" \
                 :: "r"((uint32_t)(smem_addr)), "r"((uint32_t)(nCols)) : "memory")
#define TCGEN05_DEALLOC(tmem_addr, nCols) \
    asm volatile("tcgen05.dealloc.cta_group::1.sync.aligned.b32 %0, %1;" \
                 :: "r"(tmem_addr), "r"((uint32_t)(nCols)))
#define TCGEN05_RELINQUISH() \
    asm volatile("tcgen05.relinquish_alloc_permit.cta_group::1.sync.aligned;")
#define TCGEN05_COMMIT(mbar) \
    asm volatile("tcgen05.commit.cta_group::1.mbarrier::arrive::one.shared::cluster.b64 [%0];" \
                 :: "r"((uint32_t)(mbar)) : "memory")
#define TCGEN05_FENCE_AFTER()  asm volatile("tcgen05.fence::after_thread_sync;" ::: "memory")
#define TCGEN05_FENCE_BEFORE() asm volatile("tcgen05.fence::before_thread_sync;" ::: "memory")
#define TCGEN05_WAIT_LD()      asm volatile("tcgen05.wait::ld.sync.aligned;" ::: "memory")
#define TCGEN05_WAIT_ST()      asm volatile("tcgen05.wait::st.sync.aligned;" ::: "memory")
#define FENCE_PROXY_ASYNC()    asm volatile("fence.proxy.async.shared::cta;" ::: "memory")

#define TCGEN05_LD_32X32B_X32(r, tmem_addr) \
    asm volatile( \
        "tcgen05.ld.sync.aligned.32x32b.x32.b32 " \
        "{%0, %1, %2, %3, %4, %5, %6, %7, " \
        " %8, %9, %10, %11, %12, %13, %14, %15, " \
        " %16, %17, %18, %19, %20, %21, %22, %23, " \
        " %24, %25, %26, %27, %28, %29, %30, %31}, [%32];" \
        : "=r"((r)[0]),  "=r"((r)[1]),  "=r"((r)[2]),  "=r"((r)[3]), \
          "=r"((r)[4]),  "=r"((r)[5]),  "=r"((r)[6]),  "=r"((r)[7]), \
          "=r"((r)[8]),  "=r"((r)[9]),  "=r"((r)[10]), "=r"((r)[11]), \
          "=r"((r)[12]), "=r"((r)[13]), "=r"((r)[14]), "=r"((r)[15]), \
          "=r"((r)[16]), "=r"((r)[17]), "=r"((r)[18]), "=r"((r)[19]), \
          "=r"((r)[20]), "=r"((r)[21]), "=r"((r)[22]), "=r"((r)[23]), \
          "=r"((r)[24]), "=r"((r)[25]), "=r"((r)[26]), "=r"((r)[27]), \
          "=r"((r)[28]), "=r"((r)[29]), "=r"((r)[30]), "=r"((r)[31]) \
        : "r"(tmem_addr))

#define TCGEN05_ST_32X32B_X32(tmem_addr, r) \
    asm volatile( \
        "tcgen05.st.sync.aligned.32x32b.x32.b32 [%0], " \
        "{%1, %2, %3, %4, %5, %6, %7, %8, " \
        " %9, %10, %11, %12, %13, %14, %15, %16, " \
        " %17, %18, %19, %20, %21, %22, %23, %24, " \
        " %25, %26, %27, %28, %29, %30, %31, %32};" \
        :: "r"(tmem_addr), \
           "r"((r)[0]),  "r"((r)[1]),  "r"((r)[2]),  "r"((r)[3]), \
           "r"((r)[4]),  "r"((r)[5]),  "r"((r)[6]),  "r"((r)[7]), \
           "r"((r)[8]),  "r"((r)[9]),  "r"((r)[10]), "r"((r)[11]), \
           "r"((r)[12]), "r"((r)[13]), "r"((r)[14]), "r"((r)[15]), \
           "r"((r)[16]), "r"((r)[17]), "r"((r)[18]), "r"((r)[19]), \
           "r"((r)[20]), "r"((r)[21]), "r"((r)[22]), "r"((r)[23]), \
           "r"((r)[24]), "r"((r)[25]), "r"((r)[26]), "r"((r)[27]), \
           "r"((r)[28]), "r"((r)[29]), "r"((r)[30]), "r"((r)[31]) \
        : "memory")

// TS-mode fp16 MMA: A in TMEM, B via SMEM descriptor, fp32 accum.
__device__ __forceinline__ void mma_f16_ts(uint32_t d, uint32_t a_tmem, uint64_t b,
                                           uint32_t idesc, uint32_t en) {
#if defined(__CUDA_ARCH_FEAT_SM103_ALL)
    asm volatile(
        "{\n\t"
        ".reg .pred p;\n\t"
        "setp.ne.u32 p, %5, 0;\n\t"
        "tcgen05.mma.cta_group::1.kind::f16 [%0], [%1], %2, %3, {%4, %4, %4, %4}, p;\n\t"
        "}"
        :: "r"(d), "r"(a_tmem), "l"(b), "r"(idesc), "r"(0u), "r"(en)
        : "memory");
#endif
}

// ---------------------------------------------------------------- kernel 1: x -> fp16, chunk-transposed
__global__ __launch_bounds__(256) void k_convert(const float* __restrict__ x) {
    __shared__ uint4 tile[32][33];
    const int c0 = blockIdx.x * 32;
    const int m0 = blockIdx.y * 32;
    const int tid = threadIdx.x;
#pragma unroll
    for (int p = 0; p < 4; ++p) {
        int idx = p * 256 + tid;
        int cc = idx & 31, mm = idx >> 5;
        const float4* src = reinterpret_cast<const float4*>(
            x + (size_t)(m0 + mm) * IN_F + (size_t)(c0 + cc) * 8);
        float4 a = __ldg(src), b = __ldg(src + 1);
        __half2 h0 = __floats2half2_rn(a.x, a.y);
        __half2 h1 = __floats2half2_rn(a.z, a.w);
        __half2 h2 = __floats2half2_rn(b.x, b.y);
        __half2 h3 = __floats2half2_rn(b.z, b.w);
        uint4 o;
        o.x = *reinterpret_cast<uint32_t*>(&h0);
        o.y = *reinterpret_cast<uint32_t*>(&h1);
        o.z = *reinterpret_cast<uint32_t*>(&h2);
        o.w = *reinterpret_cast<uint32_t*>(&h3);
        tile[cc][mm] = o;
    }
    __syncthreads();
#pragma unroll
    for (int p = 0; p < 4; ++p) {
        int idx = p * 256 + tid;
        int mm = idx & 31, cc = idx >> 5;
        g_xh_T[(size_t)(c0 + cc) * TOKENS + (m0 + mm)] = tile[cc][mm];
    }
}

// ---------------------------------------------------------------- kernel 2: fused dequant GEMM (TS mode)
// CTA tile M=256, N=128; K-chunk 128 (=GSIZE); A in TMEM (2 slots x 128 cols); B in SMEM
// (2 stages x 32KB, each stage = two 128-row x 128B SW128 sub-tiles); warp-specialized.
static constexpr int BM = 256, BN = 128, BK = 128;
static constexpr int STAGES = 2;
static constexpr int NPROD = 256;
static constexpr int NTHREADS = 288;
static constexpr int B_SUB = 16384;                      // one 64-k sub-tile
static constexpr int B_BYTES = 2 * B_SUB;                // 32768 per stage
static constexpr int SMEM_CTRL = 1024;
static constexpr int EPI_WARP_BYTES = 16896;             // 32 rows x 528B
static constexpr int SMEM_TOTAL = SMEM_CTRL + 8 * EPI_WARP_BYTES; // 136192 (covers 2x32KB stages)
static constexpr int K_ITERS = IN_F / BK;                // 32
static constexpr int TMEM_D = 256;                       // D cols 256..511; A slots 0..255
static constexpr uint32_t IDESC = (1u << 4) | ((BN / 8) << 17) | ((128 / 16) << 24);
#define FULL_BAR(s)  (smem_base + 16 + 16 * (s))
#define EMPTY_BAR(s) (smem_base + 24 + 16 * (s))

__global__ __launch_bounds__(NTHREADS, 1) void k_gemm(const int* __restrict__ qweight,
                                                      const int* __restrict__ qzeros,
                                                      const float* __restrict__ scales,
                                                      const float* __restrict__ bias,
                                                      float* __restrict__ out) {
    extern __shared__ char smem[];
    const uint32_t smem_base = smem_u32(smem);
    const int tid = threadIdx.x;
    const int wid = tid >> 5;
    const int lid = tid & 31;
    const int NB = OUT_F / BN;                           // 86
    const int n0 = (blockIdx.x % NB) * BN;
    const int m0 = (blockIdx.x / NB) * BM;

#if defined(__CUDA_ARCH_FEAT_SM103_ALL)
    // =================== warp-specialized TS-mode pipeline ===================
    if (wid == 0) TCGEN05_ALLOC(smem_base + 0, 512);
    if (tid == 0) {
#pragma unroll
        for (int s = 0; s < STAGES; s++) {
            MBARRIER_INIT(FULL_BAR(s), NPROD);           // 256 producer arrives
            MBARRIER_INIT(EMPTY_BAR(s), 1);
            MBARRIER_ARRIVE(EMPTY_BAR(s));               // pre-arm: phase 0 completes
        }
    }
    __syncthreads();
    uint32_t tmem;
    asm volatile("ld.shared.b32 %0, [%1];" : "=r"(tmem) : "r"(smem_base));

    if (tid < NPROD) {
        // -------- producer: A row (coalesced LDG -> STTM) + 64-k of one B column --------
        const int nc = tid & 127;                        // B column (= smem row) within tile
        const int n = n0 + nc;
        const int kh = tid >> 7;                         // 64-k half this thread dequants
        const uint32_t warp_offset = (uint32_t)(((tid & 127) >> 5) << 21);
        const uint32_t a_tm_base = tmem + (uint32_t)((tid >> 7) * 64) + warp_offset;
        const uint4* a16 = g_xh_T + (size_t)(m0 + tid);

        uint32_t abuf[64];                               // 128 fp16 = this row's A chunk
        uint32_t qbuf[2][8];
        __half2 scbuf[2], zcbuf[2];

        auto ldg_A = [&](int j) {
#pragma unroll
            for (int c = 0; c < 16; c++) {               // lanes read consecutive m: coalesced
                uint4 v = __ldg(a16 + (size_t)(j * 16 + c) * TOKENS);
                abuf[4 * c + 0] = v.x; abuf[4 * c + 1] = v.y;
                abuf[4 * c + 2] = v.z; abuf[4 * c + 3] = v.w;
            }
        };
        auto ldg_q = [&](int j, int b) {
            const int* qw = qweight + (size_t)(j * 16 + kh * 8) * OUT_F + n;
#pragma unroll
            for (int i = 0; i < 8; i++) qbuf[b][i] = (uint32_t)__ldg(qw + (size_t)i * OUT_F);
            float sc = __ldg(scales + (size_t)j * OUT_F + n);          // group = j (BK == GSIZE)
            uint32_t qz = (uint32_t)__ldg(qzeros + (size_t)j * (OUT_F / 8) + (n >> 3));
            int z1 = (int)((qz >> ((n & 7) * 4)) & 0xF) + 1;
            scbuf[b] = __half2half2(__float2half_rn(sc));
            zcbuf[b] = __half2half2(__float2half_rn((float)(1024 + z1)));  // exact in fp16
        };

        ldg_A(0);
        ldg_q(0, 0);

        for (int it = 0; it < K_ITERS; ++it) {
            const int s = it & 1;
            const int r = it >> 1;
            MBARRIER_WAIT_PARITY(EMPTY_BAR(s), r & 1);   // stage free (MMA round r-1 done)

            // A: regs -> TMEM slot s (two warp-collective x32 stores; regs read at issue)
            TCGEN05_ST_32X32B_X32(a_tm_base + s * 128, abuf);
            TCGEN05_ST_32X32B_X32(a_tm_base + s * 128 + 32, abuf + 32);
            if (it + 1 < K_ITERS) ldg_A(it + 1);         // refill immediately; ~full period of slack

            // B: dequant 64 k-values -> sub-tile kh, row nc (8 x STS.128)
            {
                char* bptr = smem + SMEM_CTRL + s * B_BYTES + kh * B_SUB;
                const int b = it & 1;
                const __half2 sc2 = scbuf[b], zc2 = zcbuf[b];
#pragma unroll
                for (int i = 0; i < 8; i++) {
                    uint32_t qv = qbuf[b][i];
                    uint32_t w[4];
#pragma unroll
                    for (int p = 0; p < 4; p++) {
                        uint32_t t = qv >> (8 * p);
                        uint32_t u = (t & 0xFu) | ((t & 0xF0u) << 12) | 0x64006400u;
                        __half2 vh = *reinterpret_cast<__half2*>(&u);
                        __half2 dh = __hsub2(vh, zc2);                       // exact v - z1
                        __half2 wh = __hmul2(dh, sc2);
                        w[p] = *reinterpret_cast<uint32_t*>(&wh);
                    }
                    uint32_t off = (uint32_t)(nc * 128 + i * 16);
                    *reinterpret_cast<uint4*>(bptr + SWZ128(off)) = make_uint4(w[0], w[1], w[2], w[3]);
                }
            }
            if (it + 1 < K_ITERS) ldg_q(it + 1, (it + 1) & 1);

            TCGEN05_WAIT_ST();                           // TMEM drain hidden under dequant ALU
            TCGEN05_FENCE_BEFORE();
            MBARRIER_ARRIVE(FULL_BAR(s));
        }
    } else if (tid == NPROD) {
        // -------- MMA thread --------
        for (int it = 0; it < K_ITERS; ++it) {
            const int s = it & 1;
            const int r = it >> 1;
            MBARRIER_WAIT_PARITY(FULL_BAR(s), r & 1);
            FENCE_PROXY_ASYNC();                          // STS B -> async proxy
            TCGEN05_FENCE_AFTER();                        // STTM A visibility
            const uint32_t sb = smem_base + SMEM_CTRL + s * B_BYTES;
            uint64_t bd0 = MAKE_SMEM_DESC(sb);
            uint64_t bd1 = MAKE_SMEM_DESC(sb + B_SUB);
            const uint32_t a_s = tmem + s * 128;
#pragma unroll
            for (int kk = 0; kk < 8; kk++) {              // 8 x K=16 steps
                uint64_t bd = (kk < 4) ? (bd0 + kk * 2) : (bd1 + (kk - 4) * 2);
                mma_f16_ts(tmem + TMEM_D,       a_s + kk * 8,      bd, IDESC, (uint32_t)(it | kk));
                mma_f16_ts(tmem + TMEM_D + 128, a_s + 64 + kk * 8, bd, IDESC, (uint32_t)(it | kk));
            }
            TCGEN05_COMMIT(EMPTY_BAR(s));
        }
    }

    // Last commit: it=31 -> empty[1] phase 16 (parity 0). In-order completion covers whole chain.
    MBARRIER_WAIT_PARITY(EMPTY_BAR(1), 0);
    __syncthreads();
    TCGEN05_FENCE_AFTER();

    // ---- epilogue (warps 0-7): TMEM -> SMEM transpose -> coalesced STG ----
    if (wid < 8) {
        char* wsm = smem + SMEM_CTRL + wid * EPI_WARP_BYTES;   // 32 rows x 132 f32 (528B)
        const uint32_t dz = tmem + TMEM_D + (uint32_t)((wid >> 2) * 128);
        const int mrow = m0 + (wid >> 2) * 128 + (wid & 3) * 32;
#pragma unroll
        for (int ch = 0; ch < 4; ++ch) {                 // 4 x 32-col chunks
            uint32_t d[32];
            TCGEN05_LD_32X32B_X32(d, dz + ch * 32);
            TCGEN05_WAIT_LD();
#pragma unroll
            for (int c = 0; c < 32; c += 4)
                *reinterpret_cast<uint4*>(wsm + lid * 528 + (ch * 32 + c) * 4) =
                    make_uint4(d[c], d[c + 1], d[c + 2], d[c + 3]);
        }
        __syncwarp();
        float4 b4 = *reinterpret_cast<const float4*>(bias + n0 + lid * 4);
#pragma unroll 4
        for (int j = 0; j < 32; ++j) {
            float4 v = *reinterpret_cast<float4*>(wsm + j * 528 + lid * 16);
            v.x += b4.x; v.y += b4.y; v.z += b4.z; v.w += b4.w;
            *reinterpret_cast<float4*>(out + (size_t)(mrow + j) * OUT_F + n0 + lid * 4) = v;
        }
    }

    TCGEN05_FENCE_BEFORE();
    __syncthreads();
    if (wid == 0) {
        TCGEN05_RELINQUISH();
        TCGEN05_DEALLOC(tmem, 512);
    }
#else
    // =================== trivial fallback (never selected on sm_103a hardware) ===================
    if (tid < 128) {
        const int nn = n0 + tid;
        for (int m = m0; m < m0 + BM; ++m) {
            float acc = bias[nn];
            for (int k = 0; k < IN_F; ++k) {
                int g = k >> 7;
                uint32_t q = (uint32_t)qweight[(size_t)(k >> 3) * OUT_F + nn];
                int v = (int)((q >> ((k & 7) * 4)) & 0xF);
                uint32_t qz = (uint32_t)qzeros[(size_t)g * (OUT_F / 8) + (nn >> 3)];
                int z1 = (int)((qz >> ((nn & 7) * 4)) & 0xF) + 1;
                const uint4 xv = g_xh_T[(size_t)(k >> 3) * TOKENS + m];
                const __half* xh = reinterpret_cast<const __half*>(&xv);
                acc += __half2float(xh[k & 7]) * (scales[(size_t)g * OUT_F + nn] * (float)(v - z1));
            }
            out[(size_t)m * OUT_F + nn] = acc;
        }
    }
#endif
}

// ---------------------------------------------------------------- launch
extern "C" void kernel_launch(void* const* d_in, const int* in_sizes, int n_in,
                              void* d_out, int out_size) {
    const float* x       = (const float*)d_in[0];
    const int*   qweight = (const int*)  d_in[1];
    const int*   qzeros  = (const int*)  d_in[2];
    const float* scales  = (const float*)d_in[3];
    // d_in[4] = g_idx (implicitly k/128, hardcoded)
    const float* bias    = (const float*)d_in[5];
    float* out = (float*)d_out;

    k_convert<<<dim3(IN_F / 8 / 32, TOKENS / 32), 256>>>(x);

    cudaFuncSetAttribute(k_gemm, cudaFuncAttributeMaxDynamicSharedMemorySize, SMEM_TOTAL);
    k_gemm<<<(OUT_F / BN) * (TOKENS / BM), NTHREADS, SMEM_TOTAL>>>(qweight, qzeros, scales, bias, out);
}